// round 16
// baseline (speedup 1.0000x reference)
#include <cuda_runtime.h>
#include <cuda_fp16.h>
#include <math_constants.h>

#define B_  8
#define L_  1024
#define S_  1024
#define D_  256
#define V_  256
#define H_  8

#define N_TOK (B_*L_)
#define SCALE_F 0.17677669529663687f
#define LOG2E_F 1.4426950408889634f

__host__ __device__ __forceinline__ int permp(int p)
{
    return ((p & 3) << 1) | (p >> 2);
}

// ---------------- scratch (static device arrays: allocation-free) ----------
__device__ __half g_qf[N_TOK*D_];
__device__ __half g_kf[N_TOK*D_];
__device__ __half g_vf[N_TOK*D_];
__device__ __half g_wqs[D_*D_], g_wqo[D_*D_], g_wks[D_*D_];
__device__ __half g_wko[D_*D_], g_wv[D_*D_], g_fcwh[V_*V_];
__device__ __half g_mh[N_TOK*S_];     // mask * log2e, fp16

__device__ __half g_qs[N_TOK*D_];
__device__ __half g_qo[N_TOK*D_];
__device__ __half g_ks[N_TOK*D_];
__device__ __half g_ko[N_TOK*D_];
__device__ __half g_vh[N_TOK*D_];

// ---------------- exp2 on the MUFU pipe -------------------------------------
__device__ __forceinline__ float ex2f(float x)
{
    float r;
    asm("ex2.approx.ftz.f32 %0, %1;" : "=f"(r) : "f"(x));
    return r;
}

__device__ __forceinline__ void mma_f16(float c[4], const unsigned a[4],
                                        const unsigned b[2])
{
    asm("mma.sync.aligned.m16n8k16.row.col.f32.f16.f16.f32 "
        "{%0,%1,%2,%3}, {%4,%5,%6,%7}, {%8,%9}, {%0,%1,%2,%3};"
        : "+f"(c[0]), "+f"(c[1]), "+f"(c[2]), "+f"(c[3])
        : "r"(a[0]), "r"(a[1]), "r"(a[2]), "r"(a[3]),
          "r"(b[0]), "r"(b[1]));
}

// ---------------------------------------------------------------------------
// Prep: fp32 -> fp16 pair-permuted (K=256 rows).
// ---------------------------------------------------------------------------
struct Prep9 {
    const float* src[9];
    __half*      dst[9];
    int          n[9];
};

__global__ __launch_bounds__(256)
void prep_kernel(Prep9 P)
{
    int z = blockIdx.y;
    int idx = blockIdx.x * 256 + threadIdx.x;
    int i2 = idx * 2;
    if (i2 >= P.n[z]) return;
    float2 v = *reinterpret_cast<const float2*>(&P.src[z][i2]);
    int c = i2 & 255;
    int pos = (c & ~15) + permp((c & 15) >> 1) * 2;
    *reinterpret_cast<__half2*>(&P.dst[z][(size_t)(i2 >> 8) * 256 + pos]) =
        __floats2half2_rn(v.x, v.y);
}

__global__ __launch_bounds__(256)
void prep_mask_kernel(const float* __restrict__ m, __half* __restrict__ mh)
{
    size_t i = ((size_t)blockIdx.x * 256 + threadIdx.x) * 4;
    float4 v = *reinterpret_cast<const float4*>(&m[i]);
    __half2 a = __floats2half2_rn(v.x * LOG2E_F, v.y * LOG2E_F);
    __half2 b = __floats2half2_rn(v.z * LOG2E_F, v.w * LOG2E_F);
    uint2 o;
    o.x = *reinterpret_cast<unsigned*>(&a);
    o.y = *reinterpret_cast<unsigned*>(&b);
    *reinterpret_cast<uint2*>(&mh[i]) = o;
}

// ---------------------------------------------------------------------------
// gemm16: warp tile 32x32, block tile 128m x 64n, 256 thr, 3 blocks/SM.
// mode 1: fp16 permuted | mode 2: v blocked
// ---------------------------------------------------------------------------
__device__ __forceinline__ void gemm16_body(
    const unsigned* __restrict__ A, const unsigned* __restrict__ Bw,
    void* __restrict__ Cout, float scale, int mode)
{
    const int t    = threadIdx.x;
    const int w    = t >> 5;
    const int lane = t & 31;
    const int gid  = lane >> 2;
    const int tid4 = lane & 3;

    const int m0 = blockIdx.y * 128 + (w & 3) * 32;
    const int n0 = blockIdx.x * 64 + (w >> 2) * 32;

    float c[2][4][4];
#pragma unroll
    for (int rt = 0; rt < 2; rt++)
#pragma unroll
        for (int nt = 0; nt < 4; nt++)
#pragma unroll
            for (int e = 0; e < 4; e++) c[rt][nt][e] = 0.f;

#pragma unroll 4
    for (int kg = 0; kg < 16; kg++) {
        const int ko = kg * 8 + 2 * tid4;
        unsigned a[2][4];
#pragma unroll
        for (int rt = 0; rt < 2; rt++) {
            uint2 lo = *reinterpret_cast<const uint2*>(
                &A[(size_t)(m0 + rt * 16 + gid) * 128 + ko]);
            uint2 hi = *reinterpret_cast<const uint2*>(
                &A[(size_t)(m0 + rt * 16 + gid + 8) * 128 + ko]);
            a[rt][0] = lo.x; a[rt][1] = hi.x;
            a[rt][2] = lo.y; a[rt][3] = hi.y;
        }
#pragma unroll
        for (int nt = 0; nt < 4; nt++) {
            uint2 bb = *reinterpret_cast<const uint2*>(
                &Bw[(size_t)(n0 + nt * 8 + gid) * 128 + ko]);
            unsigned bfr[2] = {bb.x, bb.y};
            mma_f16(c[0][nt], a[0], bfr);
            mma_f16(c[1][nt], a[1], bfr);
        }
    }

    if (mode == 1) {
        __half* Ch = (__half*)Cout;
#pragma unroll
        for (int nt = 0; nt < 4; nt++) {
            int col = n0 + nt * 8 + 2 * tid4;
            int pos = (col & ~15) + permp((col & 15) >> 1) * 2;
#pragma unroll
            for (int rt = 0; rt < 2; rt++) {
                int r0 = m0 + rt * 16 + gid;
                *reinterpret_cast<__half2*>(&Ch[(size_t)r0 * 256 + pos]) =
                    __floats2half2_rn(c[rt][nt][0] * scale,
                                      c[rt][nt][1] * scale);
                *reinterpret_cast<__half2*>(&Ch[(size_t)(r0 + 8) * 256 + pos]) =
                    __floats2half2_rn(c[rt][nt][2] * scale,
                                      c[rt][nt][3] * scale);
            }
        }
    } else {
        __half* Ch = (__half*)Cout;
#pragma unroll
        for (int rt = 0; rt < 2; rt++)
#pragma unroll
            for (int rp = 0; rp < 2; rp++) {
                int r  = m0 + rt * 16 + gid + 8 * rp;
                int bb2 = r >> 10;
                int s  = r & 1023;
                int ph = permp((s & 15) >> 1) * 2 + (s & 1);
                size_t base0 = ((size_t)(bb2 * 64 + (s >> 4))) * 8;
#pragma unroll
                for (int nt = 0; nt < 4; nt++) {
#pragma unroll
                    for (int e = 0; e < 2; e++) {
                        int n = n0 + nt * 8 + 2 * tid4 + e;
                        size_t hi = ((base0 + (n >> 5)) * 32 + (n & 31)) * 16 + ph;
                        Ch[hi] = __float2half(c[rt][nt][2 * rp + e]);
                    }
                }
            }
    }
}

struct G5 {
    const unsigned* A[5];
    const unsigned* W[5];
    void*           C[5];
    float           sc[5];
    int             md[5];
};

__global__ __launch_bounds__(256, 3)
void proj16_kernel(G5 g)
{
    int z = blockIdx.z;
    gemm16_body(g.A[z], g.W[z], g.C[z], g.sc[z], g.md[z]);
}

// ---------------------------------------------------------------------------
// Attention + fused fc. Block = (b, 16 l-rows), 256 threads, 2 blocks/SM.
// smem: score [16][1036] fp32 (reused as sctx uints [16][136] for fc)
//       eh uint[16][516] | red [2][16][36] | inv[32] | qid 16 | kid 1024
// total 108,224 B/block -> 2 blocks/SM.
// ---------------------------------------------------------------------------
#define SC_STR 1036
#define EH_STR 516
#define AT_SMEM_BYTES ((16*SC_STR + 16*EH_STR + 1152 + 32 + 16 + 1024) * 4)

__device__ __forceinline__ void score_phase(
    int h, float* score,
    const int* qid_s, const int* kid_s,
    size_t qbase, size_t kbase, size_t mrow0,
    int cb, int gid, int tid4)
{
    unsigned aS[2][4], aO[2][4];
    {
        const size_t r0 = (qbase + gid) * D_ + h * 32;
        const size_t r1 = r0 + 8 * D_;
#pragma unroll
        for (int g = 0; g < 2; g++) {
            int off = g * 16 + 4 * tid4;
            uint2 lo = *reinterpret_cast<const uint2*>(&g_qs[r0 + off]);
            uint2 hi = *reinterpret_cast<const uint2*>(&g_qs[r1 + off]);
            aS[g][0] = lo.x; aS[g][1] = hi.x;
            aS[g][2] = lo.y; aS[g][3] = hi.y;
            lo = *reinterpret_cast<const uint2*>(&g_qo[r0 + off]);
            hi = *reinterpret_cast<const uint2*>(&g_qo[r1 + off]);
            aO[g][0] = lo.x; aO[g][1] = hi.x;
            aO[g][2] = lo.y; aO[g][3] = hi.y;
        }
    }
    int qi0 = qid_s[gid];
    int qi1 = qid_s[gid + 8];

#pragma unroll 2
    for (int nt = 0; nt < 16; nt++) {
        const int sK   = cb + nt * 8 + gid;
        const int scol = cb + nt * 8 + 2 * tid4;

        unsigned bS[2][2], bO[2][2];
        const size_t krow = (kbase + sK) * D_ + h * 32;
#pragma unroll
        for (int g = 0; g < 2; g++) {
            int off = g * 16 + 4 * tid4;
            uint2 v = *reinterpret_cast<const uint2*>(&g_ks[krow + off]);
            bS[g][0] = v.x; bS[g][1] = v.y;
            v = *reinterpret_cast<const uint2*>(&g_ko[krow + off]);
            bO[g][0] = v.x; bO[g][1] = v.y;
        }

        int2 ki = *reinterpret_cast<const int2*>(&kid_s[scol]);
        __half2 mf0 = *reinterpret_cast<const __half2*>(
            &g_mh[mrow0 + (size_t)gid * S_ + scol]);
        __half2 mf1 = *reinterpret_cast<const __half2*>(
            &g_mh[mrow0 + (size_t)(gid + 8) * S_ + scol]);

        float cS[4] = {0,0,0,0}, cO[4] = {0,0,0,0};
#pragma unroll
        for (int g = 0; g < 2; g++) {
            mma_f16(cS, aS[g], bS[g]);
            mma_f16(cO, aO[g], bO[g]);
        }

        float2 m0 = __half22float2(mf0);
        float2 m1 = __half22float2(mf1);
        float v0 = ((qi0 == ki.x) ? cS[0] : cO[0]) + m0.x;
        float v1 = ((qi0 == ki.y) ? cS[1] : cO[1]) + m0.y;
        float v2 = ((qi1 == ki.x) ? cS[2] : cO[2]) + m1.x;
        float v3 = ((qi1 == ki.y) ? cS[3] : cO[3]) + m1.y;
        *reinterpret_cast<float2*>(&score[gid * SC_STR + scol]) =
            make_float2(v0, v1);
        *reinterpret_cast<float2*>(&score[(gid + 8) * SC_STR + scol]) =
            make_float2(v2, v3);
    }
}

__device__ __forceinline__ void pv_phase(
    int h, const unsigned* __restrict__ ebase, int estride, bool skew,
    float* red, int b, int nc, int sh, int gid, int tid4)
{
    float cv[4] = {0,0,0,0};
    const size_t vb0 = ((((size_t)(b * 64 + sh * 32) * 8 + h) * 32 +
                         nc * 8 + gid)) * 8 + 2 * tid4;
    const unsigned* vh_u = reinterpret_cast<const unsigned*>(g_vh);

    const unsigned* e0 = ebase + gid * estride +
                         (skew ? (((gid >> 2) & 1) << 2) : 0);
    const unsigned* e1 = ebase + (gid + 8) * estride +
                         (skew ? ((((gid + 8) >> 2) & 1) << 2) : 0);

#pragma unroll 4
    for (int kstep = 0; kstep < 32; kstep++) {
        uint2 bvv = *reinterpret_cast<const uint2*>(
            &vh_u[vb0 + (size_t)kstep * 2048]);
        unsigned bfrag[2] = {bvv.x, bvv.y};
        const int k8 = sh * 256 + kstep * 8;
        unsigned av[4];
        av[0] = e0[k8 + tid4];
        av[1] = e1[k8 + tid4];
        av[2] = e0[k8 + tid4 + 4];
        av[3] = e1[k8 + tid4 + 4];
        mma_f16(cv, av, bfrag);
    }

#pragma unroll
    for (int rp = 0; rp < 2; rp++) {
        int row = gid + 8 * rp;
        *reinterpret_cast<float2*>(
            &red[sh * 576 + row * 36 + nc * 8 + 2 * tid4]) =
            make_float2(cv[2*rp], cv[2*rp+1]);
    }
}

__global__ __launch_bounds__(256, 2)
void attn_kernel(const int* __restrict__ qid,
                 const int* __restrict__ kid,
                 float* __restrict__ attn_out,
                 float* __restrict__ out,
                 const float* __restrict__ fcb)
{
    extern __shared__ float sm[];
    float*    score = sm;                            // [16][1036] fp32
    unsigned* eh    = (unsigned*)(sm + 16 * SC_STR); // [16][516] half2
    float*    red   = sm + 16 * SC_STR + 16 * EH_STR;// [2][16][36]
    float*    inv   = red + 1152;                    // [32]
    int*      qid_s = (int*)(inv + 32);              // [16]
    int*      kid_s = qid_s + 16;                    // [1024]

    const int b    = blockIdx.y;
    const int l0   = blockIdx.x * 16;
    const int t    = threadIdx.x;
    const int lane = t & 31;
    const int w    = t >> 5;                  // 0..7
    const int gid  = lane >> 2;
    const int tid4 = lane & 3;

    const size_t qbase = (size_t)(b * L_ + l0);
    const size_t kbase = (size_t)(b * S_);
    const size_t mrow0 = qbase * S_;

    const int cb = w * 128;                   // score cols for this warp
    const int nc = w & 3;                     // PV col group
    const int sh = w >> 2;                    // PV s-half

    for (int i = t; i < S_; i += 256) kid_s[i] = kid[b * S_ + i];
    if (t < 16) qid_s[t] = qid[b * L_ + l0 + t];

    unsigned ctxr[8];   // per-thread ctx half2: row = t>>4, d0 = (t&15)*2

    for (int ph = 0; ph < 4; ph++) {
        const int h0 = 2 * ph, h1 = h0 + 1;
        __syncthreads();

        // ===== head h0: score =====
        score_phase(h0, score, qid_s, kid_s, qbase, kbase, mrow0,
                    cb, gid, tid4);
        __syncthreads();

        // ===== softmax h0 -> ehA (fp16), inv[row] =====
        {
            int row = 2 * w + (lane >> 4);   // handled below per warp: 2 rows
        }
#pragma unroll
        for (int rr = 0; rr < 2; rr++) {
            int row = 2 * w + rr;
            float4* pr = (float4*)(score + row * SC_STR);
            unsigned* er = eh + row * EH_STR;
            float mx = -CUDART_INF_F;
#pragma unroll
            for (int u8 = 0; u8 < 8; u8++) {
                float4 x = pr[lane + 32 * u8];
                mx = fmaxf(mx, fmaxf(fmaxf(x.x, x.y), fmaxf(x.z, x.w)));
            }
#pragma unroll
            for (int o = 16; o > 0; o >>= 1)
                mx = fmaxf(mx, __shfl_xor_sync(0xffffffffu, mx, o));
            float s = 0.f;
#pragma unroll
            for (int u8 = 0; u8 < 8; u8++) {
                int idx = lane + 32 * u8;
                float4 x = pr[idx];
                x.x = ex2f(x.x - mx); x.y = ex2f(x.y - mx);
                x.z = ex2f(x.z - mx); x.w = ex2f(x.w - mx);
                s += (x.x + x.y) + (x.z + x.w);
                __half2 h01 = __floats2half2_rn(x.x, x.y);
                __half2 h23 = __floats2half2_rn(x.z, x.w);
                uint2 ev;
                ev.x = *reinterpret_cast<unsigned*>(&h01);
                ev.y = *reinterpret_cast<unsigned*>(&h23);
                *reinterpret_cast<uint2*>(&er[2 * idx]) = ev;
            }
#pragma unroll
            for (int o = 16; o > 0; o >>= 1)
                s += __shfl_xor_sync(0xffffffffu, s, o);
            if (lane == 0) inv[row] = 1.0f / s;
        }
        __syncthreads();

        // ===== PV h0 (reads ehA) =====
        pv_phase(h0, eh, EH_STR, false, red, b, nc, sh, gid, tid4);
        __syncthreads();

        // ===== ctx h0 (to regs) + score h1 =====
        {
            int row = t >> 4;
            int d0  = (t & 15) * 2;
            float s0 = red[row * 36 + d0]     + red[576 + row * 36 + d0];
            float s1 = red[row * 36 + d0 + 1] + red[576 + row * 36 + d0 + 1];
            float iv = inv[row];
            __half2 hv = __floats2half2_rn(s0 * iv, s1 * iv);
            ctxr[h0] = *reinterpret_cast<unsigned*>(&hv);
        }
        score_phase(h1, score, qid_s, kid_s, qbase, kbase, mrow0,
                    cb, gid, tid4);
        __syncthreads();

        // ===== softmax h1: in-place fp16 downpack + combined RMW =====
#pragma unroll
        for (int rr = 0; rr < 2; rr++) {
            int row = 2 * w + rr;
            float4* pr = (float4*)(score + row * SC_STR);
            unsigned* eb = (unsigned*)score + row * SC_STR +
                           (((row >> 2) & 1) << 2);
            float4* out4 = reinterpret_cast<float4*>(
                attn_out + mrow0 + (size_t)row * S_);

            float mx = -CUDART_INF_F;
#pragma unroll
            for (int u8 = 0; u8 < 8; u8++) {
                float4 x = pr[lane + 32 * u8];
                mx = fmaxf(mx, fmaxf(fmaxf(x.x, x.y), fmaxf(x.z, x.w)));
            }
#pragma unroll
            for (int o = 16; o > 0; o >>= 1)
                mx = fmaxf(mx, __shfl_xor_sync(0xffffffffu, mx, o));

            float4 ov[8];
            if (ph > 0) {
#pragma unroll
                for (int u8 = 0; u8 < 8; u8++) ov[u8] = out4[lane + 32 * u8];
            }

            float s = 0.f;
#pragma unroll
            for (int u8 = 0; u8 < 8; u8++) {
                int idx = lane + 32 * u8;
                float4 x = pr[idx];
                x.x = ex2f(x.x - mx); x.y = ex2f(x.y - mx);
                x.z = ex2f(x.z - mx); x.w = ex2f(x.w - mx);
                s += (x.x + x.y) + (x.z + x.w);
                __half2 h01 = __floats2half2_rn(x.x, x.y);
                __half2 h23 = __floats2half2_rn(x.z, x.w);
                uint2 ev;
                ev.x = *reinterpret_cast<unsigned*>(&h01);
                ev.y = *reinterpret_cast<unsigned*>(&h23);
                *reinterpret_cast<uint2*>(&eb[2 * idx]) = ev;
            }
#pragma unroll
            for (int o = 16; o > 0; o >>= 1)
                s += __shfl_xor_sync(0xffffffffu, s, o);
            float iv1 = 1.0f / s;
            if (lane == 0) inv[16 + row] = iv1;

            float sv0 = inv[row] * 0.125f;
            float sv1 = iv1 * 0.125f;
            const uint2* eA2 = reinterpret_cast<const uint2*>(eh + row * EH_STR);
#pragma unroll
            for (int u8 = 0; u8 < 8; u8++) {
                int idx = lane + 32 * u8;
                uint2 a2 = eA2[idx];
                uint2 b2 = *reinterpret_cast<const uint2*>(&eb[2 * idx]);
                float2 a01 = __half22float2(*reinterpret_cast<__half2*>(&a2.x));
                float2 a23 = __half22float2(*reinterpret_cast<__half2*>(&a2.y));
                float2 b01 = __half22float2(*reinterpret_cast<__half2*>(&b2.x));
                float2 b23 = __half22float2(*reinterpret_cast<__half2*>(&b2.y));
                float4 o;
                if (ph == 0) {
                    o.x = a01.x * sv0 + b01.x * sv1;
                    o.y = a01.y * sv0 + b01.y * sv1;
                    o.z = a23.x * sv0 + b23.x * sv1;
                    o.w = a23.y * sv0 + b23.y * sv1;
                } else {
                    o.x = fmaf(a01.x, sv0, fmaf(b01.x, sv1, ov[u8].x));
                    o.y = fmaf(a01.y, sv0, fmaf(b01.y, sv1, ov[u8].y));
                    o.z = fmaf(a23.x, sv0, fmaf(b23.x, sv1, ov[u8].z));
                    o.w = fmaf(a23.y, sv0, fmaf(b23.y, sv1, ov[u8].w));
                }
                out4[idx] = o;
            }
        }
        __syncthreads();

        // ===== PV h1 (packed e in score strip, uint stride 1036) =====
        pv_phase(h1, (const unsigned*)score, SC_STR, true,
                 red, b, nc, sh, gid, tid4);
        __syncthreads();

        // ===== ctx h1 (to regs) =====
        {
            int row = t >> 4;
            int d0  = (t & 15) * 2;
            float s0 = red[row * 36 + d0]     + red[576 + row * 36 + d0];
            float s1 = red[row * 36 + d0 + 1] + red[576 + row * 36 + d0 + 1];
            float iv = inv[16 + row];
            __half2 hv = __floats2half2_rn(s0 * iv, s1 * iv);
            ctxr[h1] = *reinterpret_cast<unsigned*>(&hv);
        }
    }

    // ================== fused fc ==================
    __syncthreads();
    unsigned* sctx = (unsigned*)score;   // [16][136] uints, permuted fp16 ctx
    {
        int row = t >> 4;
        int d0  = (t & 15) * 2;
#pragma unroll
        for (int h = 0; h < 8; h++) {
            int n = h * 32 + d0;
            int pos = (n & ~15) + permp((n & 15) >> 1) * 2;
            sctx[row * 136 + (pos >> 1)] = ctxr[h];
        }
    }
    __syncthreads();

    // warp w -> output cols w*32 .. w*32+31, all 16 rows
    {
        const unsigned* fw = reinterpret_cast<const unsigned*>(g_fcwh);
        float c[4][4];
#pragma unroll
        for (int nt = 0; nt < 4; nt++)
#pragma unroll
            for (int e = 0; e < 4; e++) c[nt][e] = 0.f;

#pragma unroll 4
        for (int kg = 0; kg < 16; kg++) {
            const int ko = kg * 8 + 2 * tid4;
            unsigned a[4];
            uint2 lo = *reinterpret_cast<const uint2*>(&sctx[gid * 136 + ko]);
            uint2 hi = *reinterpret_cast<const uint2*>(
                &sctx[(gid + 8) * 136 + ko]);
            a[0] = lo.x; a[1] = hi.x;
            a[2] = lo.y; a[3] = hi.y;
#pragma unroll
            for (int nt = 0; nt < 4; nt++) {
                uint2 bb = *reinterpret_cast<const uint2*>(
                    &fw[(size_t)(w * 32 + nt * 8 + gid) * 128 + ko]);
                unsigned bfr[2] = {bb.x, bb.y};
                mma_f16(c[nt], a, bfr);
            }
        }

#pragma unroll
        for (int nt = 0; nt < 4; nt++) {
            int col = w * 32 + nt * 8 + 2 * tid4;
            float b0 = fcb[col], b1 = fcb[col + 1];
            *reinterpret_cast<float2*>(&out[(qbase + gid) * 256 + col]) =
                make_float2(c[nt][0] + b0, c[nt][1] + b1);
            *reinterpret_cast<float2*>(&out[(qbase + gid + 8) * 256 + col]) =
                make_float2(c[nt][2] + b0, c[nt][3] + b1);
        }
    }
}

// ---------------------------------------------------------------------------
extern "C" void kernel_launch(void* const* d_in, const int* in_sizes, int n_in,
                              void* d_out, int out_size)
{
    const float* q    = (const float*)d_in[0];
    const float* k    = (const float*)d_in[1];
    const float* v    = (const float*)d_in[2];
    const int*   qid  = (const int*)d_in[3];
    const int*   kid  = (const int*)d_in[4];
    const float* mask = (const float*)d_in[5];
    const float* wqs  = (const float*)d_in[6];
    const float* wqo  = (const float*)d_in[7];
    const float* wks  = (const float*)d_in[8];
    const float* wko  = (const float*)d_in[9];
    const float* wv   = (const float*)d_in[10];
    const float* fcw  = (const float*)d_in[11];
    const float* fcb  = (const float*)d_in[12];

    float* out      = (float*)d_out;
    float* attn_out = out + (size_t)B_ * L_ * V_;

    void *p_qf, *p_kf, *p_vf, *p_wqs, *p_wqo, *p_wks, *p_wko, *p_wv, *p_fcw;
    void *p_qs, *p_qo, *p_ks, *p_ko, *p_vh, *p_mh;
    cudaGetSymbolAddress(&p_qf,  g_qf);
    cudaGetSymbolAddress(&p_kf,  g_kf);
    cudaGetSymbolAddress(&p_vf,  g_vf);
    cudaGetSymbolAddress(&p_wqs, g_wqs);
    cudaGetSymbolAddress(&p_wqo, g_wqo);
    cudaGetSymbolAddress(&p_wks, g_wks);
    cudaGetSymbolAddress(&p_wko, g_wko);
    cudaGetSymbolAddress(&p_wv,  g_wv);
    cudaGetSymbolAddress(&p_fcw, g_fcwh);
    cudaGetSymbolAddress(&p_qs,  g_qs);
    cudaGetSymbolAddress(&p_qo,  g_qo);
    cudaGetSymbolAddress(&p_ks,  g_ks);
    cudaGetSymbolAddress(&p_ko,  g_ko);
    cudaGetSymbolAddress(&p_vh,  g_vh);
    cudaGetSymbolAddress(&p_mh,  g_mh);

    cudaFuncSetAttribute(attn_kernel,
                         cudaFuncAttributeMaxDynamicSharedMemorySize,
                         AT_SMEM_BYTES);

    Prep9 P;
    P.src[0] = q;   P.dst[0] = (__half*)p_qf;  P.n[0] = N_TOK * D_;
    P.src[1] = k;   P.dst[1] = (__half*)p_kf;  P.n[1] = N_TOK * D_;
    P.src[2] = v;   P.dst[2] = (__half*)p_vf;  P.n[2] = N_TOK * D_;
    P.src[3] = wqs; P.dst[3] = (__half*)p_wqs; P.n[3] = D_ * D_;
    P.src[4] = wqo; P.dst[4] = (__half*)p_wqo; P.n[4] = D_ * D_;
    P.src[5] = wks; P.dst[5] = (__half*)p_wks; P.n[5] = D_ * D_;
    P.src[6] = wko; P.dst[6] = (__half*)p_wko; P.n[6] = D_ * D_;
    P.src[7] = wv;  P.dst[7] = (__half*)p_wv;  P.n[7] = D_ * D_;
    P.src[8] = fcw; P.dst[8] = (__half*)p_fcw; P.n[8] = V_ * V_;
    dim3 pgrid(N_TOK * D_ / 512, 9);
    prep_kernel<<<pgrid, 256>>>(P);

    prep_mask_kernel<<<(N_TOK * S_) / 1024, 256>>>(mask, (__half*)p_mh);

    G5 g;
    g.A[0] = (const unsigned*)p_qf; g.W[0] = (const unsigned*)p_wqs;
    g.C[0] = p_qs; g.sc[0] = SCALE_F * LOG2E_F; g.md[0] = 1;
    g.A[1] = (const unsigned*)p_qf; g.W[1] = (const unsigned*)p_wqo;
    g.C[1] = p_qo; g.sc[1] = SCALE_F * LOG2E_F; g.md[1] = 1;
    g.A[2] = (const unsigned*)p_kf; g.W[2] = (const unsigned*)p_wks;
    g.C[2] = p_ks; g.sc[2] = 1.0f;   g.md[2] = 1;
    g.A[3] = (const unsigned*)p_kf; g.W[3] = (const unsigned*)p_wko;
    g.C[3] = p_ko; g.sc[3] = 1.0f;   g.md[3] = 1;
    g.A[4] = (const unsigned*)p_vf; g.W[4] = (const unsigned*)p_wv;
    g.C[4] = p_vh; g.sc[4] = 1.0f;   g.md[4] = 2;

    dim3 ggrid(4, N_TOK / 128, 5);
    proj16_kernel<<<ggrid, 256>>>(g);

    dim3 agrid(L_ / 16, B_);
    attn_kernel<<<agrid, 256, AT_SMEM_BYTES>>>(qid, kid, attn_out, out, fcb);
}

// round 17
// speedup vs baseline: 1.0712x; 1.0712x over previous
#include <cuda_runtime.h>
#include <cuda_fp16.h>
#include <math_constants.h>

#define B_  8
#define L_  1024
#define S_  1024
#define D_  256
#define V_  256
#define H_  8

#define N_TOK (B_*L_)
#define SCALE_F 0.17677669529663687f
#define LOG2E_F 1.4426950408889634f

__host__ __device__ __forceinline__ int permp(int p)
{
    return ((p & 3) << 1) | (p >> 2);
}

// ---------------- scratch (static device arrays: allocation-free) ----------
__device__ __half g_qf[N_TOK*D_];
__device__ __half g_kf[N_TOK*D_];
__device__ __half g_vf[N_TOK*D_];
__device__ __half g_wqs[D_*D_], g_wqo[D_*D_], g_wks[D_*D_];
__device__ __half g_wko[D_*D_], g_wv[D_*D_], g_fcwh[V_*V_];
__device__ __half g_mh[N_TOK*S_];     // mask * log2e, fp16

__device__ __half g_qs[N_TOK*D_];
__device__ __half g_qo[N_TOK*D_];
__device__ __half g_ks[N_TOK*D_];
__device__ __half g_ko[N_TOK*D_];
__device__ __half g_vh[N_TOK*D_];

// ---------------- exp2 on the MUFU pipe -------------------------------------
__device__ __forceinline__ float ex2f(float x)
{
    float r;
    asm("ex2.approx.ftz.f32 %0, %1;" : "=f"(r) : "f"(x));
    return r;
}

__device__ __forceinline__ void mma_f16(float c[4], const unsigned a[4],
                                        const unsigned b[2])
{
    asm("mma.sync.aligned.m16n8k16.row.col.f32.f16.f16.f32 "
        "{%0,%1,%2,%3}, {%4,%5,%6,%7}, {%8,%9}, {%0,%1,%2,%3};"
        : "+f"(c[0]), "+f"(c[1]), "+f"(c[2]), "+f"(c[3])
        : "r"(a[0]), "r"(a[1]), "r"(a[2]), "r"(a[3]),
          "r"(b[0]), "r"(b[1]));
}

// ---------------------------------------------------------------------------
// Prep: fp32 -> fp16 pair-permuted (K=256 rows).
// ---------------------------------------------------------------------------
struct Prep9 {
    const float* src[9];
    __half*      dst[9];
    int          n[9];
};

__global__ __launch_bounds__(256)
void prep_kernel(Prep9 P)
{
    int z = blockIdx.y;
    int idx = blockIdx.x * 256 + threadIdx.x;
    int i2 = idx * 2;
    if (i2 >= P.n[z]) return;
    float2 v = *reinterpret_cast<const float2*>(&P.src[z][i2]);
    int c = i2 & 255;
    int pos = (c & ~15) + permp((c & 15) >> 1) * 2;
    *reinterpret_cast<__half2*>(&P.dst[z][(size_t)(i2 >> 8) * 256 + pos]) =
        __floats2half2_rn(v.x, v.y);
}

__global__ __launch_bounds__(256)
void prep_mask_kernel(const float* __restrict__ m, __half* __restrict__ mh)
{
    size_t i = ((size_t)blockIdx.x * 256 + threadIdx.x) * 4;
    float4 v = *reinterpret_cast<const float4*>(&m[i]);
    __half2 a = __floats2half2_rn(v.x * LOG2E_F, v.y * LOG2E_F);
    __half2 b = __floats2half2_rn(v.z * LOG2E_F, v.w * LOG2E_F);
    uint2 o;
    o.x = *reinterpret_cast<unsigned*>(&a);
    o.y = *reinterpret_cast<unsigned*>(&b);
    *reinterpret_cast<uint2*>(&mh[i]) = o;
}

// ---------------------------------------------------------------------------
// gemm16: warp tile 32x32, block tile 128m x 64n, 256 thr, 3 blocks/SM.
// ---------------------------------------------------------------------------
__device__ __forceinline__ void gemm16_body(
    const unsigned* __restrict__ A, const unsigned* __restrict__ Bw,
    void* __restrict__ Cout, float scale, int mode)
{
    const int t    = threadIdx.x;
    const int w    = t >> 5;
    const int lane = t & 31;
    const int gid  = lane >> 2;
    const int tid4 = lane & 3;

    const int m0 = blockIdx.y * 128 + (w & 3) * 32;
    const int n0 = blockIdx.x * 64 + (w >> 2) * 32;

    float c[2][4][4];
#pragma unroll
    for (int rt = 0; rt < 2; rt++)
#pragma unroll
        for (int nt = 0; nt < 4; nt++)
#pragma unroll
            for (int e = 0; e < 4; e++) c[rt][nt][e] = 0.f;

#pragma unroll 4
    for (int kg = 0; kg < 16; kg++) {
        const int ko = kg * 8 + 2 * tid4;
        unsigned a[2][4];
#pragma unroll
        for (int rt = 0; rt < 2; rt++) {
            uint2 lo = *reinterpret_cast<const uint2*>(
                &A[(size_t)(m0 + rt * 16 + gid) * 128 + ko]);
            uint2 hi = *reinterpret_cast<const uint2*>(
                &A[(size_t)(m0 + rt * 16 + gid + 8) * 128 + ko]);
            a[rt][0] = lo.x; a[rt][1] = hi.x;
            a[rt][2] = lo.y; a[rt][3] = hi.y;
        }
#pragma unroll
        for (int nt = 0; nt < 4; nt++) {
            uint2 bb = *reinterpret_cast<const uint2*>(
                &Bw[(size_t)(n0 + nt * 8 + gid) * 128 + ko]);
            unsigned bfr[2] = {bb.x, bb.y};
            mma_f16(c[0][nt], a[0], bfr);
            mma_f16(c[1][nt], a[1], bfr);
        }
    }

    if (mode == 1) {
        __half* Ch = (__half*)Cout;
#pragma unroll
        for (int nt = 0; nt < 4; nt++) {
            int col = n0 + nt * 8 + 2 * tid4;
            int pos = (col & ~15) + permp((col & 15) >> 1) * 2;
#pragma unroll
            for (int rt = 0; rt < 2; rt++) {
                int r0 = m0 + rt * 16 + gid;
                *reinterpret_cast<__half2*>(&Ch[(size_t)r0 * 256 + pos]) =
                    __floats2half2_rn(c[rt][nt][0] * scale,
                                      c[rt][nt][1] * scale);
                *reinterpret_cast<__half2*>(&Ch[(size_t)(r0 + 8) * 256 + pos]) =
                    __floats2half2_rn(c[rt][nt][2] * scale,
                                      c[rt][nt][3] * scale);
            }
        }
    } else {
        __half* Ch = (__half*)Cout;
#pragma unroll
        for (int rt = 0; rt < 2; rt++)
#pragma unroll
            for (int rp = 0; rp < 2; rp++) {
                int r  = m0 + rt * 16 + gid + 8 * rp;
                int bb2 = r >> 10;
                int s  = r & 1023;
                int ph = permp((s & 15) >> 1) * 2 + (s & 1);
                size_t base0 = ((size_t)(bb2 * 64 + (s >> 4))) * 8;
#pragma unroll
                for (int nt = 0; nt < 4; nt++) {
#pragma unroll
                    for (int e = 0; e < 2; e++) {
                        int n = n0 + nt * 8 + 2 * tid4 + e;
                        size_t hi = ((base0 + (n >> 5)) * 32 + (n & 31)) * 16 + ph;
                        Ch[hi] = __float2half(c[rt][nt][2 * rp + e]);
                    }
                }
            }
    }
}

struct G5 {
    const unsigned* A[5];
    const unsigned* W[5];
    void*           C[5];
    float           sc[5];
    int             md[5];
};

__global__ __launch_bounds__(256, 3)
void proj16_kernel(G5 g)
{
    int z = blockIdx.z;
    gemm16_body(g.A[z], g.W[z], g.C[z], g.sc[z], g.md[z]);
}

// ---------------------------------------------------------------------------
// Attention + fused fc (R15 structure, 32 rows / 512 thr / 1 block/SM),
// with distance-1 register prefetch on the k- and v-fragment LDG chains.
// smem: score [32][1036] fp32 (reused as sctx uints [32][132] for fc)
//       eh uint[32][516] | red [4][32][36] | inv[64] | qid 32 | kid 1024
// ---------------------------------------------------------------------------
#define SC_STR 1036
#define EH_STR 516
#define AT_SMEM_BYTES ((32*SC_STR + 32*EH_STR + 4608 + 64 + 32 + 1024) * 4)

__device__ __forceinline__ void score_phase(
    int h, float* score,
    const int* qid_s, const int* kid_s,
    size_t qbase, size_t kbase, size_t mrow0,
    int cb, int gid, int tid4)
{
    unsigned aS[2][2][4], aO[2][2][4];
#pragma unroll
    for (int rt = 0; rt < 2; rt++) {
        const size_t r0 = (qbase + rt * 16 + gid) * D_ + h * 32;
        const size_t r1 = r0 + 8 * D_;
#pragma unroll
        for (int g = 0; g < 2; g++) {
            int off = g * 16 + 4 * tid4;
            uint2 lo = *reinterpret_cast<const uint2*>(&g_qs[r0 + off]);
            uint2 hi = *reinterpret_cast<const uint2*>(&g_qs[r1 + off]);
            aS[rt][g][0] = lo.x; aS[rt][g][1] = hi.x;
            aS[rt][g][2] = lo.y; aS[rt][g][3] = hi.y;
            lo = *reinterpret_cast<const uint2*>(&g_qo[r0 + off]);
            hi = *reinterpret_cast<const uint2*>(&g_qo[r1 + off]);
            aO[rt][g][0] = lo.x; aO[rt][g][1] = hi.x;
            aO[rt][g][2] = lo.y; aO[rt][g][3] = hi.y;
        }
    }
    int qi[2][2];
#pragma unroll
    for (int rt = 0; rt < 2; rt++) {
        qi[rt][0] = qid_s[rt * 16 + gid];
        qi[rt][1] = qid_s[rt * 16 + gid + 8];
    }

    // double-buffered B fragments: preload nt=0
    unsigned bS[2][2][2], bO[2][2][2];
    {
        const size_t krow = (kbase + cb + gid) * D_ + h * 32;
#pragma unroll
        for (int g = 0; g < 2; g++) {
            int off = g * 16 + 4 * tid4;
            uint2 v = *reinterpret_cast<const uint2*>(&g_ks[krow + off]);
            bS[0][g][0] = v.x; bS[0][g][1] = v.y;
            v = *reinterpret_cast<const uint2*>(&g_ko[krow + off]);
            bO[0][g][0] = v.x; bO[0][g][1] = v.y;
        }
    }

#pragma unroll
    for (int nt = 0; nt < 8; nt++) {
        const int cur = nt & 1, nxt = cur ^ 1;
        const int scol = cb + nt * 8 + 2 * tid4;

        // prefetch nt+1's B fragments (in flight under this nt's MMAs)
        if (nt < 7) {
            const size_t krow = (kbase + cb + (nt + 1) * 8 + gid) * D_ + h * 32;
#pragma unroll
            for (int g = 0; g < 2; g++) {
                int off = g * 16 + 4 * tid4;
                uint2 v = *reinterpret_cast<const uint2*>(&g_ks[krow + off]);
                bS[nxt][g][0] = v.x; bS[nxt][g][1] = v.y;
                v = *reinterpret_cast<const uint2*>(&g_ko[krow + off]);
                bO[nxt][g][0] = v.x; bO[nxt][g][1] = v.y;
            }
        }

        int2 ki = *reinterpret_cast<const int2*>(&kid_s[scol]);
        __half2 mf[2][2];
#pragma unroll
        for (int rt = 0; rt < 2; rt++)
#pragma unroll
            for (int rp = 0; rp < 2; rp++) {
                int row = rt * 16 + gid + 8 * rp;
                mf[rt][rp] = *reinterpret_cast<const __half2*>(
                    &g_mh[mrow0 + (size_t)row * S_ + scol]);
            }

        float cS[2][4] = {{0,0,0,0},{0,0,0,0}};
        float cO[2][4] = {{0,0,0,0},{0,0,0,0}};
#pragma unroll
        for (int g = 0; g < 2; g++)
#pragma unroll
            for (int rt = 0; rt < 2; rt++) {
                mma_f16(cS[rt], aS[rt][g], bS[cur][g]);
                mma_f16(cO[rt], aO[rt][g], bO[cur][g]);
            }

#pragma unroll
        for (int rt = 0; rt < 2; rt++)
#pragma unroll
            for (int rp = 0; rp < 2; rp++) {
                int row = rt * 16 + gid + 8 * rp;
                float s0 = (qi[rt][rp] == ki.x) ? cS[rt][2*rp]   : cO[rt][2*rp];
                float s1 = (qi[rt][rp] == ki.y) ? cS[rt][2*rp+1] : cO[rt][2*rp+1];
                float2 m2 = __half22float2(mf[rt][rp]);
                *reinterpret_cast<float2*>(&score[row * SC_STR + scol]) =
                    make_float2(s0 + m2.x, s1 + m2.y);
            }
    }
}

__device__ __forceinline__ void pv_phase(
    int h, const unsigned* __restrict__ ebase, int estride, bool skew,
    float* red, int b, int nc, int sh, int gid, int tid4)
{
    float cv[2][4] = {{0,0,0,0},{0,0,0,0}};
    const size_t vb0 = ((((size_t)(b * 64 + sh * 16) * 8 + h) * 32 +
                         nc * 8 + gid)) * 8 + 2 * tid4;
    const unsigned* vh_u = reinterpret_cast<const unsigned*>(g_vh);

    // distance-1 prefetch for v fragments
    uint2 vb[2];
    vb[0] = *reinterpret_cast<const uint2*>(&vh_u[vb0]);

#pragma unroll
    for (int kstep = 0; kstep < 16; kstep++) {
        const int cur = kstep & 1, nxt = cur ^ 1;
        if (kstep < 15)
            vb[nxt] = *reinterpret_cast<const uint2*>(
                &vh_u[vb0 + (size_t)(kstep + 1) * 2048]);
        unsigned bfrag[2] = {vb[cur].x, vb[cur].y};
        const int k8 = sh * 128 + kstep * 8;
#pragma unroll
        for (int rt = 0; rt < 2; rt++) {
            int row0 = rt * 16 + gid;
            int row1 = row0 + 8;
            const unsigned* e0 = ebase + row0 * estride +
                                 (skew ? (((row0 >> 2) & 1) << 2) : 0);
            const unsigned* e1 = ebase + row1 * estride +
                                 (skew ? (((row1 >> 2) & 1) << 2) : 0);
            unsigned av[4];
            av[0] = e0[k8 + tid4];
            av[1] = e1[k8 + tid4];
            av[2] = e0[k8 + tid4 + 4];
            av[3] = e1[k8 + tid4 + 4];
            mma_f16(cv[rt], av, bfrag);
        }
    }

#pragma unroll
    for (int rt = 0; rt < 2; rt++)
#pragma unroll
        for (int rp = 0; rp < 2; rp++) {
            int row = rt * 16 + gid + 8 * rp;
            *reinterpret_cast<float2*>(
                &red[sh * 1152 + row * 36 + nc * 8 + 2 * tid4]) =
                make_float2(cv[rt][2*rp], cv[rt][2*rp+1]);
        }
}

__global__ __launch_bounds__(512, 1)
void attn_kernel(const int* __restrict__ qid,
                 const int* __restrict__ kid,
                 float* __restrict__ attn_out,
                 float* __restrict__ out,
                 const float* __restrict__ fcb)
{
    extern __shared__ float sm[];
    float*    score = sm;                            // [32][1036] fp32
    unsigned* eh    = (unsigned*)(sm + 32 * SC_STR); // [32][516] half2
    float*    red   = sm + 32 * SC_STR + 32 * EH_STR;// [4][32][36]
    float*    inv   = red + 4608;                    // [64]
    int*      qid_s = (int*)(inv + 64);              // [32]
    int*      kid_s = qid_s + 32;                    // [1024]

    const int b    = blockIdx.y;
    const int l0   = blockIdx.x * 32;
    const int t    = threadIdx.x;
    const int lane = t & 31;
    const int w    = t >> 5;
    const int gid  = lane >> 2;
    const int tid4 = lane & 3;

    const size_t qbase = (size_t)(b * L_ + l0);
    const size_t kbase = (size_t)(b * S_);
    const size_t mrow0 = qbase * S_;

    const int cb = w * 64;
    const int nc = w & 3;
    const int sh = w >> 2;

    for (int i = t; i < S_; i += 512) kid_s[i] = kid[b * S_ + i];
    if (t < 32) qid_s[t] = qid[b * L_ + l0 + t];

    unsigned ctxr[8];   // per-thread ctx half2 for (row=t>>4, d0=(t&15)*2)

    for (int ph = 0; ph < 4; ph++) {
        const int h0 = 2 * ph, h1 = h0 + 1;
        __syncthreads();

        // ===== head h0: score =====
        score_phase(h0, score, qid_s, kid_s, qbase, kbase, mrow0,
                    cb, gid, tid4);
        __syncthreads();

        // ===== softmax h0 -> ehA (fp16), inv[row] =====
#pragma unroll
        for (int rr = 0; rr < 2; rr++) {
            int row = 2 * w + rr;
            float4* pr = (float4*)(score + row * SC_STR);
            unsigned* er = eh + row * EH_STR;
            float mx = -CUDART_INF_F;
#pragma unroll
            for (int u8 = 0; u8 < 8; u8++) {
                float4 x = pr[lane + 32 * u8];
                mx = fmaxf(mx, fmaxf(fmaxf(x.x, x.y), fmaxf(x.z, x.w)));
            }
#pragma unroll
            for (int o = 16; o > 0; o >>= 1)
                mx = fmaxf(mx, __shfl_xor_sync(0xffffffffu, mx, o));
            float s = 0.f;
#pragma unroll
            for (int u8 = 0; u8 < 8; u8++) {
                int idx = lane + 32 * u8;
                float4 x = pr[idx];
                x.x = ex2f(x.x - mx); x.y = ex2f(x.y - mx);
                x.z = ex2f(x.z - mx); x.w = ex2f(x.w - mx);
                s += (x.x + x.y) + (x.z + x.w);
                __half2 h01 = __floats2half2_rn(x.x, x.y);
                __half2 h23 = __floats2half2_rn(x.z, x.w);
                uint2 ev;
                ev.x = *reinterpret_cast<unsigned*>(&h01);
                ev.y = *reinterpret_cast<unsigned*>(&h23);
                *reinterpret_cast<uint2*>(&er[2 * idx]) = ev;
            }
#pragma unroll
            for (int o = 16; o > 0; o >>= 1)
                s += __shfl_xor_sync(0xffffffffu, s, o);
            if (lane == 0) inv[row] = 1.0f / s;
        }
        __syncthreads();

        // ===== PV h0 (reads ehA) =====
        pv_phase(h0, eh, EH_STR, false, red, b, nc, sh, gid, tid4);
        __syncthreads();

        // ===== ctx h0 (to regs) + score h1 =====
        {
            int row = t >> 4;
            int d0  = (t & 15) * 2;
            float s0 = red[row * 36 + d0]        + red[1152 + row * 36 + d0] +
                       red[2304 + row * 36 + d0] + red[3456 + row * 36 + d0];
            float s1 = red[row * 36 + d0 + 1]        + red[1152 + row * 36 + d0 + 1] +
                       red[2304 + row * 36 + d0 + 1] + red[3456 + row * 36 + d0 + 1];
            float iv = inv[row];
            __half2 hv = __floats2half2_rn(s0 * iv, s1 * iv);
            ctxr[h0] = *reinterpret_cast<unsigned*>(&hv);
        }
        score_phase(h1, score, qid_s, kid_s, qbase, kbase, mrow0,
                    cb, gid, tid4);
        __syncthreads();

        // ===== softmax h1: in-place fp16 downpack + combined RMW =====
#pragma unroll
        for (int rr = 0; rr < 2; rr++) {
            int row = 2 * w + rr;
            float4* pr = (float4*)(score + row * SC_STR);
            unsigned* eb = (unsigned*)score + row * SC_STR +
                           (((row >> 2) & 1) << 2);
            float4* out4 = reinterpret_cast<float4*>(
                attn_out + mrow0 + (size_t)row * S_);

            float mx = -CUDART_INF_F;
#pragma unroll
            for (int u8 = 0; u8 < 8; u8++) {
                float4 x = pr[lane + 32 * u8];
                mx = fmaxf(mx, fmaxf(fmaxf(x.x, x.y), fmaxf(x.z, x.w)));
            }
#pragma unroll
            for (int o = 16; o > 0; o >>= 1)
                mx = fmaxf(mx, __shfl_xor_sync(0xffffffffu, mx, o));

            float4 ov[8];
            if (ph > 0) {
#pragma unroll
                for (int u8 = 0; u8 < 8; u8++) ov[u8] = out4[lane + 32 * u8];
            }

            float s = 0.f;
#pragma unroll
            for (int u8 = 0; u8 < 8; u8++) {
                int idx = lane + 32 * u8;
                float4 x = pr[idx];
                x.x = ex2f(x.x - mx); x.y = ex2f(x.y - mx);
                x.z = ex2f(x.z - mx); x.w = ex2f(x.w - mx);
                s += (x.x + x.y) + (x.z + x.w);
                __half2 h01 = __floats2half2_rn(x.x, x.y);
                __half2 h23 = __floats2half2_rn(x.z, x.w);
                uint2 ev;
                ev.x = *reinterpret_cast<unsigned*>(&h01);
                ev.y = *reinterpret_cast<unsigned*>(&h23);
                *reinterpret_cast<uint2*>(&eb[2 * idx]) = ev;
            }
#pragma unroll
            for (int o = 16; o > 0; o >>= 1)
                s += __shfl_xor_sync(0xffffffffu, s, o);
            float iv1 = 1.0f / s;
            if (lane == 0) inv[32 + row] = iv1;

            float sv0 = inv[row] * 0.125f;
            float sv1 = iv1 * 0.125f;
            const uint2* eA2 = reinterpret_cast<const uint2*>(eh + row * EH_STR);
#pragma unroll
            for (int u8 = 0; u8 < 8; u8++) {
                int idx = lane + 32 * u8;
                uint2 a2 = eA2[idx];
                uint2 b2 = *reinterpret_cast<const uint2*>(&eb[2 * idx]);
                float2 a01 = __half22float2(*reinterpret_cast<__half2*>(&a2.x));
                float2 a23 = __half22float2(*reinterpret_cast<__half2*>(&a2.y));
                float2 b01 = __half22float2(*reinterpret_cast<__half2*>(&b2.x));
                float2 b23 = __half22float2(*reinterpret_cast<__half2*>(&b2.y));
                float4 o;
                if (ph == 0) {
                    o.x = a01.x * sv0 + b01.x * sv1;
                    o.y = a01.y * sv0 + b01.y * sv1;
                    o.z = a23.x * sv0 + b23.x * sv1;
                    o.w = a23.y * sv0 + b23.y * sv1;
                } else {
                    o.x = fmaf(a01.x, sv0, fmaf(b01.x, sv1, ov[u8].x));
                    o.y = fmaf(a01.y, sv0, fmaf(b01.y, sv1, ov[u8].y));
                    o.z = fmaf(a23.x, sv0, fmaf(b23.x, sv1, ov[u8].z));
                    o.w = fmaf(a23.y, sv0, fmaf(b23.y, sv1, ov[u8].w));
                }
                out4[idx] = o;
            }
        }
        __syncthreads();

        // ===== PV h1 (packed e in score strip, uint stride 1036) =====
        pv_phase(h1, (const unsigned*)score, SC_STR, true,
                 red, b, nc, sh, gid, tid4);
        __syncthreads();

        // ===== ctx h1 (to regs) =====
        {
            int row = t >> 4;
            int d0  = (t & 15) * 2;
            float s0 = red[row * 36 + d0]        + red[1152 + row * 36 + d0] +
                       red[2304 + row * 36 + d0] + red[3456 + row * 36 + d0];
            float s1 = red[row * 36 + d0 + 1]        + red[1152 + row * 36 + d0 + 1] +
                       red[2304 + row * 36 + d0 + 1] + red[3456 + row * 36 + d0 + 1];
            float iv = inv[32 + row];
            __half2 hv = __floats2half2_rn(s0 * iv, s1 * iv);
            ctxr[h1] = *reinterpret_cast<unsigned*>(&hv);
        }
    }

    // ================== fused fc ==================
    __syncthreads();
    unsigned* sctx = (unsigned*)score;   // [32][132] uints (permuted fp16 ctx)
    {
        int row = t >> 4;
        int d0  = (t & 15) * 2;
#pragma unroll
        for (int h = 0; h < 8; h++) {
            int n = h * 32 + d0;
            int pos = (n & ~15) + permp((n & 15) >> 1) * 2;
            sctx[row * 132 + (pos >> 1)] = ctxr[h];
        }
    }
    __syncthreads();

    // warp w -> output cols w*16 .. w*16+15, all 32 rows
    {
        const unsigned* fw = reinterpret_cast<const unsigned*>(g_fcwh);
        float c[2][2][4];
#pragma unroll
        for (int rt = 0; rt < 2; rt++)
#pragma unroll
            for (int nt = 0; nt < 2; nt++)
#pragma unroll
                for (int e = 0; e < 4; e++) c[rt][nt][e] = 0.f;

#pragma unroll 4
        for (int kg = 0; kg < 16; kg++) {
            const int ko = kg * 8 + 2 * tid4;
            unsigned a[2][4];
#pragma unroll
            for (int rt = 0; rt < 2; rt++) {
                uint2 lo = *reinterpret_cast<const uint2*>(
                    &sctx[(rt * 16 + gid) * 132 + ko]);
                uint2 hi = *reinterpret_cast<const uint2*>(
                    &sctx[(rt * 16 + gid + 8) * 132 + ko]);
                a[rt][0] = lo.x; a[rt][1] = hi.x;
                a[rt][2] = lo.y; a[rt][3] = hi.y;
            }
#pragma unroll
            for (int nt = 0; nt < 2; nt++) {
                uint2 bb = *reinterpret_cast<const uint2*>(
                    &fw[(size_t)(w * 16 + nt * 8 + gid) * 128 + ko]);
                unsigned bfr[2] = {bb.x, bb.y};
                mma_f16(c[0][nt], a[0], bfr);
                mma_f16(c[1][nt], a[1], bfr);
            }
        }

#pragma unroll
        for (int nt = 0; nt < 2; nt++) {
            int col = w * 16 + nt * 8 + 2 * tid4;
            float b0 = fcb[col], b1 = fcb[col + 1];
#pragma unroll
            for (int rt = 0; rt < 2; rt++) {
                int r0 = rt * 16 + gid;
                *reinterpret_cast<float2*>(
                    &out[(qbase + r0) * 256 + col]) =
                    make_float2(c[rt][nt][0] + b0, c[rt][nt][1] + b1);
                *reinterpret_cast<float2*>(
                    &out[(qbase + r0 + 8) * 256 + col]) =
                    make_float2(c[rt][nt][2] + b0, c[rt][nt][3] + b1);
            }
        }
    }
}

// ---------------------------------------------------------------------------
extern "C" void kernel_launch(void* const* d_in, const int* in_sizes, int n_in,
                              void* d_out, int out_size)
{
    const float* q    = (const float*)d_in[0];
    const float* k    = (const float*)d_in[1];
    const float* v    = (const float*)d_in[2];
    const int*   qid  = (const int*)d_in[3];
    const int*   kid  = (const int*)d_in[4];
    const float* mask = (const float*)d_in[5];
    const float* wqs  = (const float*)d_in[6];
    const float* wqo  = (const float*)d_in[7];
    const float* wks  = (const float*)d_in[8];
    const float* wko  = (const float*)d_in[9];
    const float* wv   = (const float*)d_in[10];
    const float* fcw  = (const float*)d_in[11];
    const float* fcb  = (const float*)d_in[12];

    float* out      = (float*)d_out;
    float* attn_out = out + (size_t)B_ * L_ * V_;

    void *p_qf, *p_kf, *p_vf, *p_wqs, *p_wqo, *p_wks, *p_wko, *p_wv, *p_fcw;
    void *p_qs, *p_qo, *p_ks, *p_ko, *p_vh, *p_mh;
    cudaGetSymbolAddress(&p_qf,  g_qf);
    cudaGetSymbolAddress(&p_kf,  g_kf);
    cudaGetSymbolAddress(&p_vf,  g_vf);
    cudaGetSymbolAddress(&p_wqs, g_wqs);
    cudaGetSymbolAddress(&p_wqo, g_wqo);
    cudaGetSymbolAddress(&p_wks, g_wks);
    cudaGetSymbolAddress(&p_wko, g_wko);
    cudaGetSymbolAddress(&p_wv,  g_wv);
    cudaGetSymbolAddress(&p_fcw, g_fcwh);
    cudaGetSymbolAddress(&p_qs,  g_qs);
    cudaGetSymbolAddress(&p_qo,  g_qo);
    cudaGetSymbolAddress(&p_ks,  g_ks);
    cudaGetSymbolAddress(&p_ko,  g_ko);
    cudaGetSymbolAddress(&p_vh,  g_vh);
    cudaGetSymbolAddress(&p_mh,  g_mh);

    cudaFuncSetAttribute(attn_kernel,
                         cudaFuncAttributeMaxDynamicSharedMemorySize,
                         AT_SMEM_BYTES);

    Prep9 P;
    P.src[0] = q;   P.dst[0] = (__half*)p_qf;  P.n[0] = N_TOK * D_;
    P.src[1] = k;   P.dst[1] = (__half*)p_kf;  P.n[1] = N_TOK * D_;
    P.src[2] = v;   P.dst[2] = (__half*)p_vf;  P.n[2] = N_TOK * D_;
    P.src[3] = wqs; P.dst[3] = (__half*)p_wqs; P.n[3] = D_ * D_;
    P.src[4] = wqo; P.dst[4] = (__half*)p_wqo; P.n[4] = D_ * D_;
    P.src[5] = wks; P.dst[5] = (__half*)p_wks; P.n[5] = D_ * D_;
    P.src[6] = wko; P.dst[6] = (__half*)p_wko; P.n[6] = D_ * D_;
    P.src[7] = wv;  P.dst[7] = (__half*)p_wv;  P.n[7] = D_ * D_;
    P.src[8] = fcw; P.dst[8] = (__half*)p_fcw; P.n[8] = V_ * V_;
    dim3 pgrid(N_TOK * D_ / 512, 9);
    prep_kernel<<<pgrid, 256>>>(P);

    prep_mask_kernel<<<(N_TOK * S_) / 1024, 256>>>(mask, (__half*)p_mh);

    G5 g;
    g.A[0] = (const unsigned*)p_qf; g.W[0] = (const unsigned*)p_wqs;
    g.C[0] = p_qs; g.sc[0] = SCALE_F * LOG2E_F; g.md[0] = 1;
    g.A[1] = (const unsigned*)p_qf; g.W[1] = (const unsigned*)p_wqo;
    g.C[1] = p_qo; g.sc[1] = SCALE_F * LOG2E_F; g.md[1] = 1;
    g.A[2] = (const unsigned*)p_kf; g.W[2] = (const unsigned*)p_wks;
    g.C[2] = p_ks; g.sc[2] = 1.0f;   g.md[2] = 1;
    g.A[3] = (const unsigned*)p_kf; g.W[3] = (const unsigned*)p_wko;
    g.C[3] = p_ko; g.sc[3] = 1.0f;   g.md[3] = 1;
    g.A[4] = (const unsigned*)p_vf; g.W[4] = (const unsigned*)p_wv;
    g.C[4] = p_vh; g.sc[4] = 1.0f;   g.md[4] = 2;

    dim3 ggrid(4, N_TOK / 128, 5);
    proj16_kernel<<<ggrid, 256>>>(g);

    dim3 agrid(L_ / 32, B_);
    attn_kernel<<<agrid, 512, AT_SMEM_BYTES>>>(qid, kid, attn_out, out, fcb);
}